// round 16
// baseline (speedup 1.0000x reference)
#include <cuda_runtime.h>
#include <math.h>

// ---------------------------------------------------------------------------
// ReservoirBlock: B=8, T=2048, D=768, R=3072, HR=768, HF=3072.  All fp32.
// ---------------------------------------------------------------------------

#define NTOK 16384          // B*T
#define DIM  768
#define RDIM 3072
#define TLEN 2048
#define NB   8

// recurrence tiling: 6 j-tiles x 24 k-chunks = 144 persistent blocks
#define JT   6
#define NKC  24
#define JW   512            // cols per block  (RDIM/JT)
#define KW   128            // k per block     (RDIM/NKC)
#define KS   104            // k rows cached in smem (rest streamed from L2)
#define KR   (KW - KS)      // 24 streamed rows
#define RBLK (JT * NKC)     // 144

typedef unsigned long long ull;

// ------------------------------ scratch ------------------------------------
__device__ __align__(16) float g_buf1[(size_t)NTOK * RDIM];   // xu ; later rln
__device__ __align__(16) float g_buf2[(size_t)NTOK * RDIM];   // r_raw ; later ffn hidden
__device__ __align__(16) float g_ln  [(size_t)NTOK * DIM];
__device__ __align__(16) float g_t1  [(size_t)NTOK * DIM];
__device__ __align__(16) float g_r   [(size_t)NTOK * DIM];
__device__ __align__(16) float g_gz  [(size_t)NTOK * 2 * DIM];
__device__ __align__(16) float g_g1  [(size_t)NTOK * DIM];
__device__ __align__(16) float g_m   [(size_t)NTOK * DIM];
// chunk partials, ping-pong by step parity: [par][kc][batch-pair][j]
__device__ __align__(16) float2 g_part[2][NKC][4][RDIM];
// reduced h state, ping-pong by (t+1)&1: layout [j][b]
__device__ __align__(16) float g_h[2][RDIM * NB];
// two-level global barrier state (zero-init; monotonic across replays)
__device__ unsigned g_cnt_grp[12 * 64];   // 12 counters, 256B apart
__device__ unsigned g_cnt_master;
__device__ unsigned g_sense_rel;
// per-kc group barrier (6 arrivals each; monotonic)
__device__ unsigned g_kc_cnt[NKC * 64];
__device__ unsigned g_kc_rel[NKC * 64];

// --------------------------- f32x2 helpers ---------------------------------
__device__ __forceinline__ ull pk2(float x, float y) {
    ull r; asm("mov.b64 %0, {%1, %2};" : "=l"(r) : "f"(x), "f"(y)); return r;
}
__device__ __forceinline__ void fma2(ull &d, ull a, ull b) {
    asm("fma.rn.f32x2 %0, %1, %2, %0;" : "+l"(d) : "l"(a), "l"(b));
}
__device__ __forceinline__ float2 up2(ull v) {
    float2 f; asm("mov.b64 {%0, %1}, %2;" : "=f"(f.x), "=f"(f.y) : "l"(v)); return f;
}

// --------------------------- two-level grid barrier -------------------------
__device__ __forceinline__ void grid_bar2(int grp, unsigned &sense) {
    __syncthreads();
    sense += 1;
    if (threadIdx.x == 0) {
        __threadfence();
        unsigned a = atomicAdd(&g_cnt_grp[grp << 6], 1u);
        if ((a % 12u) == 11u) {
            __threadfence();
            unsigned b = atomicAdd(&g_cnt_master, 1u);
            if ((b % 12u) == 11u) {
                atomicExch(&g_sense_rel, sense);
            }
        }
        while ((int)(*(volatile unsigned *)&g_sense_rel - sense) < 0) { }
        __threadfence();
    }
    __syncthreads();
}

// --------------------------- recurrence ------------------------------------
// Per block: 512 cols x 128 k.  Thread = 2 adjacent cols x 8 batches.
// W rows [0,KS) in smem; rows [KS,KW) stream from L2 via register prefetch.
// Finalize is DEDUPLICATED: the 6 blocks sharing kc split the 512 reduction
// units (128 j x 4 batch-pairs) of chunk kc; reduced+tanh'd h goes to g_h,
// then a 6-arrival kc-group barrier gates the 4KB h-slice reload.
__global__ void __launch_bounds__(256, 1)
reservoir_kernel(const float* __restrict__ W, const float* __restrict__ xu,
                 float* __restrict__ rout)
{
    extern __shared__ float sm[];
    float* W_s = sm;                 // KS*JW floats (208 KB)
    float* h_s = sm + KS * JW;       // KW*NB  floats (4 KB)

    const int tid = threadIdx.x;
    const int bid = blockIdx.x;
    const int jt  = bid / NKC;
    const int kc  = bid % NKC;
    const int grp = bid / 12;

    // base senses MUST be read before this block's first barrier arrival
    unsigned sense  = *(volatile unsigned *)&g_sense_rel;
    unsigned ksense = *(volatile unsigned *)&g_kc_rel[kc << 6];

    {
        const float4* Wg = (const float4*)(W + (size_t)(kc * KW) * RDIM + jt * JW);
        float4* Ws4 = (float4*)W_s;
        const int n4 = KS * JW / 4;
        for (int i = tid; i < n4; i += 256) {
            const int k = i >> 7;
            const int c = i & 127;
            Ws4[i] = Wg[(size_t)k * (RDIM / 4) + c];
        }
    }
    for (int i = tid; i < KW * NB; i += 256) h_s[i] = 0.0f;
    __syncthreads();

    const float* Wstream = W + (size_t)(kc * KW + KS) * RDIM + jt * JW + 2 * tid;
    const int j0 = jt * JW + 2 * tid;

    // reduction-unit assignment: units of chunk kc = (pair 0..3) x (j_local 0..127),
    // flattened u = pair*128 + j_local; block jt takes [jt*86, jt*86+redN)
    const int redN  = (jt < 5) ? 86 : 82;
    const int u     = jt * 86 + tid;            // valid iff tid < redN
    const int upair = u >> 7;
    const int ufj   = kc * KW + (u & 127);
    const size_t uxs = (size_t)TLEN * RDIM;     // batch stride in xu/r
    const size_t uxbase = (size_t)(2 * upair) * uxs + ufj;

    #pragma unroll 1
    for (int t = 0; t < TLEN; ++t) {
        const int par = t & 1;
        const int hp  = (t + 1) & 1;            // parity of h produced this step

        // ---- register prefetch: streamed W rows + this thread's xu ----
        float2 wst[KR];
        #pragma unroll
        for (int k = 0; k < KR; ++k)
            wst[k] = __ldg((const float2*)(Wstream + (size_t)k * RDIM));

        float xv0 = 0.0f, xv1 = 0.0f;
        size_t rx0 = 0, rx1 = 0;
        if (tid < redN) {
            rx0 = uxbase + (size_t)t * RDIM;
            rx1 = rx0 + uxs;
            xv0 = __ldg(xu + rx0);
            xv1 = __ldg(xu + rx1);
        }

        ull a0 = 0, a1 = 0, a2 = 0, a3 = 0;
        ull a4 = 0, a5 = 0, a6 = 0, a7 = 0;

        // --- compute: smem-resident W rows ---
        #pragma unroll 8
        for (int k = 0; k < KS; ++k) {
            const float2 w = *(const float2*)&W_s[k * JW + 2 * tid];
            const ulonglong2 hA = *(const ulonglong2*)(h_s + k * NB);
            const ulonglong2 hB = *(const ulonglong2*)(h_s + k * NB + 4);
            const ull s0 = pk2(w.x, w.x), s1 = pk2(w.y, w.y);
            fma2(a0, s0, hA.x); fma2(a1, s0, hA.y); fma2(a2, s0, hB.x); fma2(a3, s0, hB.y);
            fma2(a4, s1, hA.x); fma2(a5, s1, hA.y); fma2(a6, s1, hB.x); fma2(a7, s1, hB.y);
        }
        // --- compute: streamed rows from registers ---
        #pragma unroll
        for (int k = 0; k < KR; ++k) {
            const float2 w = wst[k];
            const ulonglong2 hA = *(const ulonglong2*)(h_s + (KS + k) * NB);
            const ulonglong2 hB = *(const ulonglong2*)(h_s + (KS + k) * NB + 4);
            const ull s0 = pk2(w.x, w.x), s1 = pk2(w.y, w.y);
            fma2(a0, s0, hA.x); fma2(a1, s0, hA.y); fma2(a2, s0, hB.x); fma2(a3, s0, hB.y);
            fma2(a4, s1, hA.x); fma2(a5, s1, hA.y); fma2(a6, s1, hB.x); fma2(a7, s1, hB.y);
        }

        // --- store chunk partials ---
        {
            const float2 p0 = up2(a0), p1 = up2(a1), p2 = up2(a2), p3 = up2(a3);
            const float2 q0 = up2(a4), q1 = up2(a5), q2 = up2(a6), q3 = up2(a7);
            __stcg((float4*)&g_part[par][kc][0][j0], make_float4(p0.x, p0.y, q0.x, q0.y));
            __stcg((float4*)&g_part[par][kc][1][j0], make_float4(p1.x, p1.y, q1.x, q1.y));
            __stcg((float4*)&g_part[par][kc][2][j0], make_float4(p2.x, p2.y, q2.x, q2.y));
            __stcg((float4*)&g_part[par][kc][3][j0], make_float4(p3.x, p3.y, q3.x, q3.y));
        }

        grid_bar2(grp, sense);

        // --- dedup finalize: this block reduces its redN units of chunk kc ---
        if (tid < redN) {
            float sx = 0.0f, sy = 0.0f;
            #pragma unroll
            for (int c = 0; c < NKC; ++c) {
                const float2 v = __ldcg(&g_part[par][c][upair][ufj]);
                sx += v.x; sy += v.y;
            }
            const float v0 = tanhf(sx + xv0);
            const float v1 = tanhf(sy + xv1);
            __stcg(rout + rx0, v0);
            __stcg(rout + rx1, v1);
            __stcg((float2*)&g_h[hp][ufj * NB + 2 * upair], make_float2(v0, v1));
        }
        __syncthreads();   // all of this block's h writes issued

        // --- kc-group barrier (6 arrivals) ---
        ksense += 1;
        if (tid == 0) {
            __threadfence();
            unsigned a = atomicAdd(&g_kc_cnt[kc << 6], 1u);
            if ((a % 6u) == 5u) {
                atomicExch(&g_kc_rel[kc << 6], ksense);
            }
            while ((int)(*(volatile unsigned *)&g_kc_rel[kc << 6] - ksense) < 0) { }
            __threadfence();
        }
        __syncthreads();

        // --- reload this block's h slice (1024 floats = 256 float4) ---
        {
            const float4 hv = __ldcg((const float4*)&g_h[hp][kc * KW * NB] + tid);
            *((float4*)h_s + tid) = hv;
        }
        __syncthreads();
    }
}

// --------------------------- activations -----------------------------------
template<int ACT>
__device__ __forceinline__ float act_apply(float v) {
    if (ACT == 1) return 0.5f * v * (1.0f + erff(v * 0.70710678118654752440f)); // exact gelu
    if (ACT == 2) return 1.0f / (1.0f + expf(-v));                              // sigmoid
    return v;
}

// --------------------------- SGEMM 128x128x32 -------------------------------
// C = act(A @ Bw + bias) * exp(*scale_log). A:MxK, Bw:KxN row-major.
// K-tile 32 (half the syncs of the 16-tile version); accumulation order per
// output element unchanged (k ascending).  2 CTAs/SM pinned via launch bounds.
// MIX: epilogue computes m = g*r + (1-g)*x and writes it to C AND out2.
template<int ACT, bool MIX>
__global__ void __launch_bounds__(256, 2)
sgemm_kernel(const float* __restrict__ A, const float* __restrict__ Bw,
             const float* __restrict__ bias, float* __restrict__ C,
             int M, int N, int K,
             const float* __restrict__ scale_log,
             const float* __restrict__ guard,
             const float* __restrict__ mix_x, const float* __restrict__ mix_r,
             float* __restrict__ out2)
{
    if (guard && guard[0] == 0.0f) return;
    __shared__ float As[32 * 132];   // A^T tile, padded
    __shared__ float Bs[32 * 128];

    const int tid = threadIdx.x;
    const int bx = blockIdx.x, by = blockIdx.y;
    const int tx = tid & 15, ty = tid >> 4;
    const size_t abase = (size_t)(by * 128) * K;
    const int cbase = bx * 128;

    ull acc[8][4];
    #pragma unroll
    for (int i = 0; i < 8; ++i)
        #pragma unroll
        for (int j = 0; j < 4; ++j) acc[i][j] = 0ull;

    for (int ko = 0; ko < K; ko += 32) {
        float4 av[4], bv[4];
        #pragma unroll
        for (int i = 0; i < 4; ++i) {
            const int fa = i * 256 + tid;
            const int ar = fa >> 3, ac = (fa & 7) << 2;       // A: 128 rows x 8 f4
            const int br = fa >> 5, bc = (fa & 31) << 2;      // B: 32 rows x 32 f4
            av[i] = *(const float4*)(A + abase + (size_t)ar * K + ko + ac);
            bv[i] = *(const float4*)(Bw + (size_t)(ko + br) * N + cbase + bc);
        }
        __syncthreads();
        #pragma unroll
        for (int i = 0; i < 4; ++i) {
            const int fa = i * 256 + tid;
            const int ar = fa >> 3, ac = (fa & 7) << 2;
            const int br = fa >> 5, bc = (fa & 31) << 2;
            As[(ac + 0) * 132 + ar] = av[i].x;
            As[(ac + 1) * 132 + ar] = av[i].y;
            As[(ac + 2) * 132 + ar] = av[i].z;
            As[(ac + 3) * 132 + ar] = av[i].w;
            *(float4*)&Bs[br * 128 + bc] = bv[i];
        }
        __syncthreads();

        #pragma unroll
        for (int kk = 0; kk < 32; ++kk) {
            const float4 a0 = *(const float4*)&As[kk * 132 + ty * 4];
            const float4 a1 = *(const float4*)&As[kk * 132 + 64 + ty * 4];
            const ulonglong2 b01 = *(const ulonglong2*)&Bs[kk * 128 + tx * 4];
            const ulonglong2 b23 = *(const ulonglong2*)&Bs[kk * 128 + tx * 4 + 64];
            ull s;
            s = pk2(a0.x, a0.x); fma2(acc[0][0], s, b01.x); fma2(acc[0][1], s, b01.y); fma2(acc[0][2], s, b23.x); fma2(acc[0][3], s, b23.y);
            s = pk2(a0.y, a0.y); fma2(acc[1][0], s, b01.x); fma2(acc[1][1], s, b01.y); fma2(acc[1][2], s, b23.x); fma2(acc[1][3], s, b23.y);
            s = pk2(a0.z, a0.z); fma2(acc[2][0], s, b01.x); fma2(acc[2][1], s, b01.y); fma2(acc[2][2], s, b23.x); fma2(acc[2][3], s, b23.y);
            s = pk2(a0.w, a0.w); fma2(acc[3][0], s, b01.x); fma2(acc[3][1], s, b01.y); fma2(acc[3][2], s, b23.x); fma2(acc[3][3], s, b23.y);
            s = pk2(a1.x, a1.x); fma2(acc[4][0], s, b01.x); fma2(acc[4][1], s, b01.y); fma2(acc[4][2], s, b23.x); fma2(acc[4][3], s, b23.y);
            s = pk2(a1.y, a1.y); fma2(acc[5][0], s, b01.x); fma2(acc[5][1], s, b01.y); fma2(acc[5][2], s, b23.x); fma2(acc[5][3], s, b23.y);
            s = pk2(a1.z, a1.z); fma2(acc[6][0], s, b01.x); fma2(acc[6][1], s, b01.y); fma2(acc[6][2], s, b23.x); fma2(acc[6][3], s, b23.y);
            s = pk2(a1.w, a1.w); fma2(acc[7][0], s, b01.x); fma2(acc[7][1], s, b01.y); fma2(acc[7][2], s, b23.x); fma2(acc[7][3], s, b23.y);
        }
    }

    float sc = 1.0f;
    if (scale_log) sc = expf(scale_log[0]);
    float4 bb0 = make_float4(0.f, 0.f, 0.f, 0.f), bb1 = bb0;
    if (bias) {
        bb0 = *(const float4*)(bias + cbase + tx * 4);
        bb1 = *(const float4*)(bias + cbase + tx * 4 + 64);
    }
    #pragma unroll
    for (int i = 0; i < 8; ++i) {
        const int r = by * 128 + ((i < 4) ? (ty * 4 + i) : (64 + ty * 4 + i - 4));
        const float2 p0 = up2(acc[i][0]), p1 = up2(acc[i][1]);
        const float2 p2 = up2(acc[i][2]), p3 = up2(acc[i][3]);
        float4 o0, o1;
        o0.x = act_apply<ACT>(p0.x + bb0.x) * sc;
        o0.y = act_apply<ACT>(p0.y + bb0.y) * sc;
        o0.z = act_apply<ACT>(p1.x + bb0.z) * sc;
        o0.w = act_apply<ACT>(p1.y + bb0.w) * sc;
        o1.x = act_apply<ACT>(p2.x + bb1.x) * sc;
        o1.y = act_apply<ACT>(p2.y + bb1.y) * sc;
        o1.z = act_apply<ACT>(p3.x + bb1.z) * sc;
        o1.w = act_apply<ACT>(p3.y + bb1.w) * sc;
        const size_t off0 = (size_t)r * N + cbase + tx * 4;
        const size_t off1 = off0 + 64;
        if (MIX) {
            const float4 xr0 = *(const float4*)(mix_x + off0);
            const float4 xr1 = *(const float4*)(mix_x + off1);
            const float4 rr0 = *(const float4*)(mix_r + off0);
            const float4 rr1 = *(const float4*)(mix_r + off1);
            o0.x = o0.x * rr0.x + (1.0f - o0.x) * xr0.x;
            o0.y = o0.y * rr0.y + (1.0f - o0.y) * xr0.y;
            o0.z = o0.z * rr0.z + (1.0f - o0.z) * xr0.z;
            o0.w = o0.w * rr0.w + (1.0f - o0.w) * xr0.w;
            o1.x = o1.x * rr1.x + (1.0f - o1.x) * xr1.x;
            o1.y = o1.y * rr1.y + (1.0f - o1.y) * xr1.y;
            o1.z = o1.z * rr1.z + (1.0f - o1.z) * xr1.z;
            o1.w = o1.w * rr1.w + (1.0f - o1.w) * xr1.w;
            *(float4*)(out2 + off0) = o0;
            *(float4*)(out2 + off1) = o1;
        }
        *(float4*)(C + off0) = o0;
        *(float4*)(C + off1) = o1;
    }
}

// --------------------------- LayerNorm -------------------------------------
__device__ __forceinline__ void blk_reduce2(float &s, float &s2) {
    const unsigned m = 0xffffffffu;
    #pragma unroll
    for (int o = 16; o; o >>= 1) { s += __shfl_xor_sync(m, s, o); s2 += __shfl_xor_sync(m, s2, o); }
    __shared__ float sh[16];
    const int w = threadIdx.x >> 5, l = threadIdx.x & 31;
    if (l == 0) { sh[w] = s; sh[8 + w] = s2; }
    __syncthreads();
    if (threadIdx.x < 32) {
        s  = (l < 8) ? sh[l]     : 0.0f;
        s2 = (l < 8) ? sh[8 + l] : 0.0f;
        #pragma unroll
        for (int o = 4; o; o >>= 1) { s += __shfl_xor_sync(m, s, o); s2 += __shfl_xor_sync(m, s2, o); }
        if (l == 0) { sh[0] = s; sh[8] = s2; }
    }
    __syncthreads();
    s = sh[0]; s2 = sh[8];
}

template<int COLS>
__global__ void __launch_bounds__(256)
ln_kernel(const float* __restrict__ in, const float* __restrict__ w,
          const float* __restrict__ bb, float* __restrict__ out,
          const float* __restrict__ guard)
{
    if (guard && guard[0] == 0.0f) return;
    constexpr int E = COLS / 256;
    const size_t base = (size_t)blockIdx.x * COLS;
    const int tid = threadIdx.x;
    float v[E];
    float s = 0.0f, s2 = 0.0f;
    #pragma unroll
    for (int e = 0; e < E; ++e) {
        const float x = in[base + e * 256 + tid];
        v[e] = x; s += x; s2 += x * x;
    }
    blk_reduce2(s, s2);
    const float mu = s * (1.0f / COLS);
    const float var = s2 * (1.0f / COLS) - mu * mu;
    const float rs = rsqrtf(var + 1e-5f);
    #pragma unroll
    for (int e = 0; e < E; ++e) {
        const int i = e * 256 + tid;
        out[base + i] = (v[e] - mu) * rs * w[i] + bb[i];
    }
}

// LN over concat([x, r]) without materializing the concat
__global__ void __launch_bounds__(256)
ln_concat_kernel(const float* __restrict__ x, const float* __restrict__ r,
                 const float* __restrict__ w, const float* __restrict__ bb,
                 float* __restrict__ out)
{
    constexpr int COLS = 2 * DIM;
    constexpr int E = COLS / 256;
    const int row = blockIdx.x;
    const int tid = threadIdx.x;
    const size_t bx = (size_t)row * DIM;
    const size_t bo = (size_t)row * COLS;
    float v[E];
    float s = 0.0f, s2 = 0.0f;
    #pragma unroll
    for (int e = 0; e < E; ++e) {
        const int i = e * 256 + tid;
        const float val = (i < DIM) ? x[bx + i] : r[bx + i - DIM];
        v[e] = val; s += val; s2 += val * val;
    }
    blk_reduce2(s, s2);
    const float mu = s * (1.0f / COLS);
    const float var = s2 * (1.0f / COLS) - mu * mu;
    const float rs = rsqrtf(var + 1e-5f);
    #pragma unroll
    for (int e = 0; e < E; ++e) {
        const int i = e * 256 + tid;
        out[bo + i] = (v[e] - mu) * rs * w[i] + bb[i];
    }
}

// --------------------------- elementwise -----------------------------------
// out already holds m (written by the MIX GEMM); only add alpha*f when a != 0.
__global__ void final_kernel(const float* __restrict__ m, const float* __restrict__ f,
                             const float* __restrict__ alpha, float* __restrict__ out)
{
    const float a = alpha[0];
    if (a == 0.0f) return;
    const size_t i = (size_t)blockIdx.x * blockDim.x + threadIdx.x;
    out[i] = m[i] + a * f[i];
}

// --------------------------- launch ----------------------------------------
extern "C" void kernel_launch(void* const* d_in, const int* in_sizes, int n_in,
                              void* d_out, int out_size)
{
    (void)in_sizes; (void)n_in; (void)out_size;
    const float* x         = (const float*)d_in[0];
    const float* ln_in_w   = (const float*)d_in[1];
    const float* ln_in_b   = (const float*)d_in[2];
    const float* U         = (const float*)d_in[3];
    const float* W         = (const float*)d_in[4];
    const float* res_ln_w  = (const float*)d_in[5];
    const float* res_ln_b  = (const float*)d_in[6];
    const float* res_w1    = (const float*)d_in[7];
    const float* res_b1    = (const float*)d_in[8];
    const float* res_w2    = (const float*)d_in[9];
    const float* res_b2    = (const float*)d_in[10];
    const float* res_logsc = (const float*)d_in[11];
    const float* mix_ln_w  = (const float*)d_in[12];
    const float* mix_ln_b  = (const float*)d_in[13];
    const float* gate_w1   = (const float*)d_in[14];
    const float* gate_b1   = (const float*)d_in[15];
    const float* gate_w2   = (const float*)d_in[16];
    const float* gate_b2   = (const float*)d_in[17];
    const float* ffn_ln_w  = (const float*)d_in[18];
    const float* ffn_ln_b  = (const float*)d_in[19];
    const float* ffn_w1    = (const float*)d_in[20];
    const float* ffn_b1    = (const float*)d_in[21];
    const float* ffn_w2    = (const float*)d_in[22];
    const float* ffn_b2    = (const float*)d_in[23];
    const float* ffn_alpha = (const float*)d_in[24];
    float* out = (float*)d_out;

    float *buf1, *buf2, *lnb, *t1b, *rb, *gzb, *g1b, *mb;
    cudaGetSymbolAddress((void**)&buf1, g_buf1);
    cudaGetSymbolAddress((void**)&buf2, g_buf2);
    cudaGetSymbolAddress((void**)&lnb,  g_ln);
    cudaGetSymbolAddress((void**)&t1b,  g_t1);
    cudaGetSymbolAddress((void**)&rb,   g_r);
    cudaGetSymbolAddress((void**)&gzb,  g_gz);
    cudaGetSymbolAddress((void**)&g1b,  g_g1);
    cudaGetSymbolAddress((void**)&mb,   g_m);

    const int nelem = NTOK * DIM;
    const int res_smem = (KS * JW + KW * NB) * 4;   // 217088 B
    cudaFuncSetAttribute(reservoir_kernel,
                         cudaFuncAttributeMaxDynamicSharedMemorySize, res_smem);

    // 1. h = LN(x)
    ln_kernel<DIM><<<NTOK, 256>>>(x, ln_in_w, ln_in_b, lnb, nullptr);
    // 2. xu = h @ U   (no bias)
    sgemm_kernel<0, false><<<dim3(RDIM / 128, NTOK / 128), 256>>>(
        lnb, U, nullptr, buf1, NTOK, RDIM, DIM, nullptr, nullptr,
        nullptr, nullptr, nullptr);
    // 3. recurrence: reads xu (buf1), writes r_raw -> buf2
    reservoir_kernel<<<RBLK, 256, res_smem>>>(W, buf1, buf2);
    // 4. rln = LN(r_raw)  (buf2 -> buf1; xu dead)
    ln_kernel<RDIM><<<NTOK, 256>>>(buf2, res_ln_w, res_ln_b, buf1, nullptr);
    // 5. t1 = gelu(rln @ res_w1 + b1)
    sgemm_kernel<1, false><<<dim3(DIM / 128, NTOK / 128), 256>>>(
        buf1, res_w1, res_b1, t1b, NTOK, DIM, RDIM, nullptr, nullptr,
        nullptr, nullptr, nullptr);
    // 6. r = exp(log_scale) * (t1 @ res_w2 + b2)
    sgemm_kernel<0, false><<<dim3(DIM / 128, NTOK / 128), 256>>>(
        t1b, res_w2, res_b2, rb, NTOK, DIM, DIM, res_logsc, nullptr,
        nullptr, nullptr, nullptr);
    // 7. gz = LN(concat(x, r))
    ln_concat_kernel<<<NTOK, 256>>>(x, rb, mix_ln_w, mix_ln_b, gzb);
    // 8. g1 = gelu(gz @ gate_w1 + b1)
    sgemm_kernel<1, false><<<dim3(DIM / 128, NTOK / 128), 256>>>(
        gzb, gate_w1, gate_b1, g1b, NTOK, DIM, 2 * DIM, nullptr, nullptr,
        nullptr, nullptr, nullptr);
    // 9. g = sigmoid(g1 @ gate_w2 + b2); fused: m = g*r + (1-g)*x -> mb AND out
    sgemm_kernel<2, true><<<dim3(DIM / 128, NTOK / 128), 256>>>(
        g1b, gate_w2, gate_b2, mb, NTOK, DIM, DIM, nullptr, nullptr,
        x, rb, out);
    // 10-12. FFN branch (skipped on-device when ffn_alpha == 0)
    ln_kernel<DIM><<<NTOK, 256>>>(mb, ffn_ln_w, ffn_ln_b, lnb, ffn_alpha);
    sgemm_kernel<1, false><<<dim3(RDIM / 128, NTOK / 128), 256>>>(
        lnb, ffn_w1, ffn_b1, buf2, NTOK, RDIM, DIM, nullptr, ffn_alpha,
        nullptr, nullptr, nullptr);
    sgemm_kernel<0, false><<<dim3(DIM / 128, NTOK / 128), 256>>>(
        buf2, ffn_w2, ffn_b2, t1b, NTOK, DIM, RDIM, nullptr, ffn_alpha,
        nullptr, nullptr, nullptr);
    // 13. out += alpha * f  (no-op when alpha == 0; out already holds m)
    final_kernel<<<nelem / 256, 256>>>(mb, t1b, ffn_alpha, out);
}